// round 1
// baseline (speedup 1.0000x reference)
#include <cuda_runtime.h>
#include <cstdint>

#define N_NODES 2000
#define E_EDGES 32000
#define BB 8
#define TT 12
#define CIN 32
#define FCH 64
#define FT 64
#define TBD 96           // T*B
#define ROW (TBD*CIN)    // 3072 floats per node row

// ---------------- scratch (device globals; no runtime alloc allowed) --------
__device__ float g_deg[N_NODES];
__device__ int   g_cnt[N_NODES];
__device__ int   g_rowptr[N_NODES + 1];
__device__ int   g_cursor[N_NODES];
__device__ int   g_ecol[E_EDGES];
__device__ float g_wval[E_EDGES];
__device__ float g_wdiag[N_NODES];
__device__ float g_x0[N_NODES * ROW];
__device__ float g_t1[N_NODES * ROW];
__device__ float g_t2[N_NODES * ROW];
__device__ float g_cheb[N_NODES * TBD * FCH];

// ---------------- graph setup ------------------------------------------------
__global__ void k_init() {
    int n = blockIdx.x * 256 + threadIdx.x;
    if (n < N_NODES) { g_deg[n] = 0.f; g_cnt[n] = 0; }
}

__global__ void k_edges(const int* __restrict__ ei, const float* __restrict__ ew) {
    int e = blockIdx.x * 256 + threadIdx.x;
    if (e >= E_EDGES) return;
    atomicAdd(&g_deg[ei[e]], ew[e]);          // deg over src rows
    atomicAdd(&g_cnt[ei[E_EDGES + e]], 1);    // in-degree count on dst
}

__global__ void k_scan() {  // 1 block, 1024 threads; 2 counts each
    __shared__ int sh[1024];
    int t = threadIdx.x;
    int c0 = (2 * t     < N_NODES) ? g_cnt[2 * t]     : 0;
    int c1 = (2 * t + 1 < N_NODES) ? g_cnt[2 * t + 1] : 0;
    int s = c0 + c1;
    sh[t] = s;
    __syncthreads();
    for (int off = 1; off < 1024; off <<= 1) {
        int v = (t >= off) ? sh[t - off] : 0;
        __syncthreads();
        sh[t] += v;
        __syncthreads();
    }
    int incl = sh[t];
    int excl = incl - s;
    if (2 * t     < N_NODES) g_rowptr[2 * t]     = excl;
    if (2 * t + 1 < N_NODES) g_rowptr[2 * t + 1] = excl + c0;
    if (t == 1023) g_rowptr[N_NODES] = incl;   // == E
}

__global__ void k_prep(const float* __restrict__ lmax) {
    int n = blockIdx.x * 256 + threadIdx.x;
    if (n >= N_NODES) return;
    g_cursor[n] = g_rowptr[n];
    g_wdiag[n]  = 2.f * g_deg[n] / lmax[0] - 1.f;   // diag of 2L/lmax - I
}

__global__ void k_scatter(const int* __restrict__ ei, const float* __restrict__ ew,
                          const float* __restrict__ lmax) {
    int e = blockIdx.x * 256 + threadIdx.x;
    if (e >= E_EDGES) return;
    int s = ei[e], d = ei[E_EDGES + e];
    int slot = atomicAdd(&g_cursor[d], 1);
    g_ecol[slot] = s;
    g_wval[slot] = -2.f * ew[e] / lmax[0] - (s == d ? 1.f : 0.f);
}

// ---------------- x0: faithful permute(2,0,1,3)+reshape(N,C,TB)+transpose ---
__global__ void k_buildx0(const float* __restrict__ X) {
    long i = (long)blockIdx.x * 256 + threadIdx.x;   // flat index into X [B,N,C,T]
    if (i >= (long)BB * N_NODES * CIN * TT) return;
    int t = (int)(i % TT);
    int c = (int)((i / TT) % CIN);
    int n = (int)((i / (TT * CIN)) % N_NODES);
    int b = (int)(i / ((long)TT * CIN * N_NODES));
    // Xt flat index ([C,B,N,T] layout)
    long idx = (((long)c * BB + b) * N_NODES + n) * TT + t;
    int n2  = (int)(idx / ROW);
    int c2  = (int)((idx / TBD) % CIN);
    int tbv = (int)(idx % TBD);
    g_x0[(long)n2 * ROW + tbv * CIN + c2] = X[i];
}

// ---------------- SpMM prop: out = L_hat @ in  (MODE 1: out = 2*L@in - x0) --
template <int MODE>
__global__ void k_prop() {
    const float* __restrict__ in  = (MODE == 0) ? g_x0 : g_t1;
    float*       __restrict__ out = (MODE == 0) ? g_t1 : g_t2;
    int n = blockIdx.x, tid = threadIdx.x;
    const float* row = in + (long)n * ROW;
    float wd = g_wdiag[n];
    float acc[12];
#pragma unroll
    for (int i = 0; i < 12; i++) acc[i] = wd * row[tid + 256 * i];

    __shared__ int   scol[128];
    __shared__ float swv[128];
    int beg = g_rowptr[n], end = g_rowptr[n + 1];
    for (int base = beg; base < end; base += 128) {
        int m = end - base; if (m > 128) m = 128;
        __syncthreads();
        if (tid < m) { scol[tid] = g_ecol[base + tid]; swv[tid] = g_wval[base + tid]; }
        __syncthreads();
        for (int k = 0; k < m; k++) {
            const float* src = in + (long)scol[k] * ROW + tid;
            float w = swv[k];
#pragma unroll
            for (int i = 0; i < 12; i++) acc[i] += w * src[256 * i];
        }
    }
    float* o = out + (long)n * ROW + tid;
    if (MODE == 1) {
        const float* x0 = g_x0 + (long)n * ROW + tid;
#pragma unroll
        for (int i = 0; i < 12; i++) o[256 * i] = 2.f * acc[i] - x0[256 * i];
    } else {
#pragma unroll
        for (int i = 0; i < 12; i++) o[256 * i] = acc[i];
    }
}

// ---------------- Cheb GEMM: cheb[n,tb,f] = relu(b + sum_k sum_c Tk*Wk) -----
__global__ void k_cheb(const float* __restrict__ Wc, const float* __restrict__ bc) {
    __shared__ float Ws[3 * 32 * 64];      // [k][c][f]
    __shared__ float bs[64];
    __shared__ float ins[3][48][33];       // padded to kill bank conflicts
    int n = blockIdx.x, tid = threadIdx.x;
    for (int i = tid; i < 6144; i += 256) Ws[i] = Wc[i];
    if (tid < 64) bs[tid] = bc[tid];
    int l = tid & 15, g = tid >> 4;        // l: f-lane [0,16), g: row group [0,16)

    for (int h = 0; h < 2; h++) {          // two halves of 48 tb rows
        __syncthreads();
        for (int i = tid; i < 4608; i += 256) {
            int k = i / 1536, r = i % 1536;
            int tl = r >> 5, c = r & 31;
            int off = n * ROW + h * 1536 + r;
            float v = (k == 0) ? g_x0[off] : (k == 1) ? g_t1[off] : g_t2[off];
            ins[k][tl][c] = v;
        }
        __syncthreads();

        float acc[3][4];
#pragma unroll
        for (int i = 0; i < 3; i++)
#pragma unroll
            for (int j = 0; j < 4; j++) acc[i][j] = bs[l + 16 * j];

        for (int c = 0; c < 32; c++) {
            float w[3][4];
#pragma unroll
            for (int k = 0; k < 3; k++)
#pragma unroll
                for (int j = 0; j < 4; j++) w[k][j] = Ws[k * 2048 + c * 64 + l + 16 * j];
#pragma unroll
            for (int i = 0; i < 3; i++) {
                int tl = g + 16 * i;
                float a0 = ins[0][tl][c], a1 = ins[1][tl][c], a2 = ins[2][tl][c];
#pragma unroll
                for (int j = 0; j < 4; j++)
                    acc[i][j] += a0 * w[0][j] + a1 * w[1][j] + a2 * w[2][j];
            }
        }
#pragma unroll
        for (int i = 0; i < 3; i++) {
            int tb = h * 48 + g + 16 * i;
            float* o = g_cheb + (long)n * (TBD * FCH) + tb * FCH;
#pragma unroll
            for (int j = 0; j < 4; j++) {
                float v = acc[i][j];
                o[l + 16 * j] = v > 0.f ? v : 0.f;
            }
        }
    }
}

// ---------------- fused temporal conv + residual + relu + LN + transpose ----
// dyn smem floats: tw 12288 | res 2048 | x 3072 | vec 256 | cheb/z 96*65=6240
#define SM_TW 0
#define SM_RS 12288
#define SM_XS 14336
#define SM_VS 17408
#define SM_CH 17664
#define SM_TOTAL (17664 + 6240)   // 23904 floats = 95616 bytes

__global__ void k_final(const float* __restrict__ X,  const float* __restrict__ tw,
                        const float* __restrict__ tbv, const float* __restrict__ rw,
                        const float* __restrict__ rb,  const float* __restrict__ lg,
                        const float* __restrict__ lb,  float* __restrict__ out) {
    extern __shared__ float sm[];
    float* TWs = sm + SM_TW;   // [tap][fc][f]
    float* RSs = sm + SM_RS;   // [c][f]
    float* XSs = sm + SM_XS;   // [b][c][t]
    float* VSs = sm + SM_VS;   // time_b | res_b | ln_g | ln_b
    float* CHs = sm + SM_CH;   // [p][f] stride 65  (later reused as z)
    int n = blockIdx.x, tid = threadIdx.x;

    for (int i = tid; i < 12288; i += 256) {
        int tap = i >> 12, fc = (i >> 6) & 63, f = i & 63;
        TWs[i] = tw[(f * 64 + fc) * 3 + tap];
    }
    for (int i = tid; i < 2048; i += 256) {
        int c = i >> 6, f = i & 63;
        RSs[i] = rw[f * 32 + c];
    }
    for (int i = tid; i < 3072; i += 256)
        XSs[i] = X[((long)(i / 384) * N_NODES + n) * 384 + (i % 384)];
    if (tid < 64) {
        VSs[tid] = tbv[tid]; VSs[64 + tid] = rb[tid];
        VSs[128 + tid] = lg[tid]; VSs[192 + tid] = lb[tid];
    }
    for (int i = tid; i < 6144; i += 256) {
        int p = i >> 6, f = i & 63;
        CHs[p * 65 + f] = g_cheb[(long)n * 6144 + i];
    }
    __syncthreads();

    int l = tid & 15, g = tid >> 4;        // f = l+16j (j<4), pairs p = g+16i (i<6)
    int pb[6], pt[6], pm[6], pp[6];
    float m0[6], m2[6];
#pragma unroll
    for (int i = 0; i < 6; i++) {
        int p = g + 16 * i;
        pb[i] = p / 12; pt[i] = p % 12;
        pm[i] = (p > 0) ? p - 1 : 0;   m0[i] = (pt[i] > 0)  ? 1.f : 0.f;
        pp[i] = (p < 95) ? p + 1 : 95; m2[i] = (pt[i] < 11) ? 1.f : 0.f;
    }
    float acc[6][4];
#pragma unroll
    for (int i = 0; i < 6; i++)
#pragma unroll
        for (int j = 0; j < 4; j++) acc[i][j] = VSs[l + 16 * j] + VSs[64 + l + 16 * j];

    // temporal conv (1x3 over t, zero-padded, per b)
    for (int fc = 0; fc < 64; fc++) {
        float w0[4], w1[4], w2[4];
#pragma unroll
        for (int j = 0; j < 4; j++) {
            int f = l + 16 * j;
            w0[j] = TWs[fc * 64 + f];
            w1[j] = TWs[4096 + fc * 64 + f];
            w2[j] = TWs[8192 + fc * 64 + f];
        }
#pragma unroll
        for (int i = 0; i < 6; i++) {
            int p = g + 16 * i;
            float cm = CHs[pm[i] * 65 + fc] * m0[i];
            float c0 = CHs[p * 65 + fc];
            float cp = CHs[pp[i] * 65 + fc] * m2[i];
#pragma unroll
            for (int j = 0; j < 4; j++)
                acc[i][j] += cm * w0[j] + c0 * w1[j] + cp * w2[j];
        }
    }
    // residual 1x1 conv on raw X
    for (int c = 0; c < 32; c++) {
        float rv[4];
#pragma unroll
        for (int j = 0; j < 4; j++) rv[j] = RSs[c * 64 + l + 16 * j];
#pragma unroll
        for (int i = 0; i < 6; i++) {
            float xv = XSs[pb[i] * 384 + c * 12 + pt[i]];
#pragma unroll
            for (int j = 0; j < 4; j++) acc[i][j] += xv * rv[j];
        }
    }

    __syncthreads();                        // all CHs reads done; reuse as z
#pragma unroll
    for (int i = 0; i < 6; i++) {
        int p = g + 16 * i;
#pragma unroll
        for (int j = 0; j < 4; j++) {
            float v = acc[i][j];
            CHs[p * 65 + l + 16 * j] = v > 0.f ? v : 0.f;
        }
    }
    __syncthreads();

    // LayerNorm over f (64) per (b,t) row; warp-shuffle reduction
    int w = tid >> 5, lane = tid & 31;
    for (int i2 = 0; i2 < 12; i2++) {
        int p = w + 8 * i2;
        float v0 = CHs[p * 65 + lane], v1 = CHs[p * 65 + lane + 32];
        float s = v0 + v1, sq = v0 * v0 + v1 * v1;
#pragma unroll
        for (int o = 16; o; o >>= 1) {
            s  += __shfl_xor_sync(0xffffffffu, s,  o);
            sq += __shfl_xor_sync(0xffffffffu, sq, o);
        }
        float mu  = s * (1.f / 64.f);
        float var = sq * (1.f / 64.f) - mu * mu;
        float rs  = rsqrtf(var + 1e-5f);
        CHs[p * 65 + lane]      = (v0 - mu) * rs * VSs[128 + lane]      + VSs[192 + lane];
        CHs[p * 65 + lane + 32] = (v1 - mu) * rs * VSs[128 + lane + 32] + VSs[192 + lane + 32];
    }
    __syncthreads();

    // transposed coalesced output: out[b,n,f,t]
    for (int cc = tid; cc < 512; cc += 256) {
        int b = cc >> 6, f = cc & 63;
        float* o = out + (((long)b * N_NODES + n) * 64 + f) * 12;
#pragma unroll
        for (int q = 0; q < 3; q++) {
            float4 v;
            v.x = CHs[(b * 12 + 4 * q + 0) * 65 + f];
            v.y = CHs[(b * 12 + 4 * q + 1) * 65 + f];
            v.z = CHs[(b * 12 + 4 * q + 2) * 65 + f];
            v.w = CHs[(b * 12 + 4 * q + 3) * 65 + f];
            *reinterpret_cast<float4*>(o + 4 * q) = v;
        }
    }
}

// ---------------- launch -----------------------------------------------------
extern "C" void kernel_launch(void* const* d_in, const int* in_sizes, int n_in,
                              void* d_out, int out_size) {
    (void)in_sizes; (void)n_in; (void)out_size;
    const float* X    = (const float*)d_in[0];
    const int*   ei   = (const int*)  d_in[1];
    const float* ew   = (const float*)d_in[2];
    const float* lmax = (const float*)d_in[3];
    const float* Wc   = (const float*)d_in[4];
    const float* bc   = (const float*)d_in[5];
    const float* tw   = (const float*)d_in[6];
    const float* tb   = (const float*)d_in[7];
    const float* rw   = (const float*)d_in[8];
    const float* rb   = (const float*)d_in[9];
    const float* lg   = (const float*)d_in[10];
    const float* lb   = (const float*)d_in[11];
    float* out = (float*)d_out;

    static bool attr_done = false;
    if (!attr_done) {
        cudaFuncSetAttribute(k_final, cudaFuncAttributeMaxDynamicSharedMemorySize,
                             SM_TOTAL * (int)sizeof(float));
        attr_done = true;
    }

    k_init   <<<(N_NODES + 255) / 256, 256>>>();
    k_edges  <<<(E_EDGES + 255) / 256, 256>>>(ei, ew);
    k_scan   <<<1, 1024>>>();
    k_prep   <<<(N_NODES + 255) / 256, 256>>>(lmax);
    k_scatter<<<(E_EDGES + 255) / 256, 256>>>(ei, ew, lmax);
    k_buildx0<<<(BB * N_NODES * CIN * TT + 255) / 256, 256>>>(X);
    k_prop<0><<<N_NODES, 256>>>();
    k_prop<1><<<N_NODES, 256>>>();
    k_cheb   <<<N_NODES, 256>>>(Wc, bc);
    k_final  <<<N_NODES, 256, SM_TOTAL * (int)sizeof(float)>>>(X, tw, tb, rw, rb, lg, lb, out);
}

// round 7
// speedup vs baseline: 1.0766x; 1.0766x over previous
#include <cuda_runtime.h>
#include <cstdint>

#define N_NODES 2000
#define E_EDGES 32000
#define BB 8
#define TT 12
#define CIN 32
#define FCH 64
#define FT 64
#define TBD 96           // T*B
#define ROW (TBD*CIN)    // 3072 floats per node row

// ---------------- packed f32x2 helpers (sm_103a) -----------------------------
__device__ __forceinline__ unsigned long long bc2(float x) {
    unsigned long long r;
    asm("mov.b64 %0, {%1, %1};" : "=l"(r) : "f"(x));
    return r;
}
__device__ __forceinline__ unsigned long long pk2(float x, float y) {
    unsigned long long r;
    asm("mov.b64 %0, {%1, %2};" : "=l"(r) : "f"(x), "f"(y));
    return r;
}
__device__ __forceinline__ float2 up2(unsigned long long v) {
    float2 f;
    asm("mov.b64 {%0, %1}, %2;" : "=f"(f.x), "=f"(f.y) : "l"(v));
    return f;
}
#define FMA2(d, a, b, c) \
    asm("fma.rn.f32x2 %0, %1, %2, %3;" : "=l"(d) : "l"(a), "l"(b), "l"(c))

// ---------------- scratch (device globals; no runtime alloc allowed) --------
__device__ float g_deg[N_NODES];
__device__ int   g_cnt[N_NODES];
__device__ int   g_rowptr[N_NODES + 1];
__device__ int   g_cursor[N_NODES];
__device__ int   g_ecol[E_EDGES];
__device__ float g_wval[E_EDGES];
__device__ float g_wdiag[N_NODES];
__device__ float g_x0[N_NODES * ROW];
__device__ float g_t1[N_NODES * ROW];
__device__ float g_t2[N_NODES * ROW];
__device__ float g_cheb[N_NODES * TBD * FCH];

// ---------------- graph setup ------------------------------------------------
__global__ void k_init() {
    int n = blockIdx.x * 256 + threadIdx.x;
    if (n < N_NODES) { g_deg[n] = 0.f; g_cnt[n] = 0; }
}

__global__ void k_edges(const int* __restrict__ ei, const float* __restrict__ ew) {
    int e = blockIdx.x * 256 + threadIdx.x;
    if (e >= E_EDGES) return;
    atomicAdd(&g_deg[ei[e]], ew[e]);          // deg over src rows
    atomicAdd(&g_cnt[ei[E_EDGES + e]], 1);    // in-degree count on dst
}

__global__ void k_scan() {  // 1 block, 1024 threads; 2 counts each
    __shared__ int sh[1024];
    int t = threadIdx.x;
    int c0 = (2 * t     < N_NODES) ? g_cnt[2 * t]     : 0;
    int c1 = (2 * t + 1 < N_NODES) ? g_cnt[2 * t + 1] : 0;
    int s = c0 + c1;
    sh[t] = s;
    __syncthreads();
    for (int off = 1; off < 1024; off <<= 1) {
        int v = (t >= off) ? sh[t - off] : 0;
        __syncthreads();
        sh[t] += v;
        __syncthreads();
    }
    int incl = sh[t];
    int excl = incl - s;
    if (2 * t     < N_NODES) g_rowptr[2 * t]     = excl;
    if (2 * t + 1 < N_NODES) g_rowptr[2 * t + 1] = excl + c0;
    if (t == 1023) g_rowptr[N_NODES] = incl;   // == E
}

__global__ void k_prep(const float* __restrict__ lmax) {
    int n = blockIdx.x * 256 + threadIdx.x;
    if (n >= N_NODES) return;
    g_cursor[n] = g_rowptr[n];
    g_wdiag[n]  = 2.f * g_deg[n] / lmax[0] - 1.f;   // diag of 2L/lmax - I
}

__global__ void k_scatter(const int* __restrict__ ei, const float* __restrict__ ew,
                          const float* __restrict__ lmax) {
    int e = blockIdx.x * 256 + threadIdx.x;
    if (e >= E_EDGES) return;
    int s = ei[e], d = ei[E_EDGES + e];
    int slot = atomicAdd(&g_cursor[d], 1);
    g_ecol[slot] = s;
    g_wval[slot] = -2.f * ew[e] / lmax[0] - (s == d ? 1.f : 0.f);
}

// ---------------- x0: faithful permute(2,0,1,3)+reshape(N,C,TB)+transpose ---
__global__ void k_buildx0(const float* __restrict__ X) {
    long i = (long)blockIdx.x * 256 + threadIdx.x;   // flat index into X [B,N,C,T]
    if (i >= (long)BB * N_NODES * CIN * TT) return;
    int t = (int)(i % TT);
    int c = (int)((i / TT) % CIN);
    int n = (int)((i / (TT * CIN)) % N_NODES);
    int b = (int)(i / ((long)TT * CIN * N_NODES));
    // Xt flat index ([C,B,N,T] layout)
    long idx = (((long)c * BB + b) * N_NODES + n) * TT + t;
    int n2  = (int)(idx / ROW);
    int c2  = (int)((idx / TBD) % CIN);
    int tbv = (int)(idx % TBD);
    g_x0[(long)n2 * ROW + tbv * CIN + c2] = X[i];
}

// ---------------- SpMM prop: out = L_hat @ in  (MODE 1: out = 2*L@in - x0) --
template <int MODE>
__global__ __launch_bounds__(256) void k_prop() {
    const float* __restrict__ inp = (MODE == 0) ? g_x0 : g_t1;
    float*       __restrict__ out = (MODE == 0) ? g_t1 : g_t2;
    int n = blockIdx.x, tid = threadIdx.x;
    const float4* row = reinterpret_cast<const float4*>(inp + (long)n * ROW);
    float wd = g_wdiag[n];
    float4 acc[3];
#pragma unroll
    for (int i = 0; i < 3; i++) {
        float4 v = row[tid + 256 * i];
        acc[i] = make_float4(wd * v.x, wd * v.y, wd * v.z, wd * v.w);
    }

    __shared__ int   scol[128];
    __shared__ float swv[128];
    int beg = g_rowptr[n], end = g_rowptr[n + 1];
    for (int base = beg; base < end; base += 128) {
        int m = end - base; if (m > 128) m = 128;
        __syncthreads();
        if (tid < m) { scol[tid] = g_ecol[base + tid]; swv[tid] = g_wval[base + tid]; }
        __syncthreads();
        for (int k = 0; k < m; k++) {
            const float4* src = reinterpret_cast<const float4*>(inp + (long)scol[k] * ROW);
            float w = swv[k];
#pragma unroll
            for (int i = 0; i < 3; i++) {
                float4 v = src[tid + 256 * i];
                acc[i].x += w * v.x; acc[i].y += w * v.y;
                acc[i].z += w * v.z; acc[i].w += w * v.w;
            }
        }
    }
    float4* o = reinterpret_cast<float4*>(out + (long)n * ROW);
    if (MODE == 1) {
        const float4* x0 = reinterpret_cast<const float4*>(g_x0 + (long)n * ROW);
#pragma unroll
        for (int i = 0; i < 3; i++) {
            float4 z = x0[tid + 256 * i];
            float4 r;
            r.x = 2.f * acc[i].x - z.x; r.y = 2.f * acc[i].y - z.y;
            r.z = 2.f * acc[i].z - z.z; r.w = 2.f * acc[i].w - z.w;
            o[tid + 256 * i] = r;
        }
    } else {
#pragma unroll
        for (int i = 0; i < 3; i++) o[tid + 256 * i] = acc[i];
    }
}

// ---------------- Cheb GEMM (f32x2 packed): cheb = relu(b + sum Tk Wk) ------
__global__ __launch_bounds__(256) void k_cheb(const float* __restrict__ Wc,
                                              const float* __restrict__ bc) {
    __shared__ __align__(16) float Ws[3 * 32 * 64];   // [k][c][f]
    __shared__ __align__(16) float bs[64];
    __shared__ float ins[3][48][33];                  // padded
    int n = blockIdx.x, tid = threadIdx.x;
    for (int i = tid; i < 6144; i += 256) Ws[i] = Wc[i];
    if (tid < 64) bs[tid] = bc[tid];
    int l = tid & 15, g = tid >> 4;        // f-quad lane l, row group g

    for (int h = 0; h < 2; h++) {          // two halves of 48 tb rows
        __syncthreads();
        for (int i = tid; i < 4608; i += 256) {
            int k = i / 1536, r = i % 1536;
            int tl = r >> 5, c = r & 31;
            int off = n * ROW + h * 1536 + r;
            float v = (k == 0) ? g_x0[off] : (k == 1) ? g_t1[off] : g_t2[off];
            ins[k][tl][c] = v;
        }
        __syncthreads();

        unsigned long long acc[3][2];
        {
            float4 b4 = *reinterpret_cast<float4*>(&bs[l * 4]);
#pragma unroll
            for (int i = 0; i < 3; i++) {
                acc[i][0] = pk2(b4.x, b4.y);
                acc[i][1] = pk2(b4.z, b4.w);
            }
        }

        for (int c = 0; c < 32; c++) {
            ulonglong2 w0 = *reinterpret_cast<ulonglong2*>(&Ws[c * 64 + l * 4]);
            ulonglong2 w1 = *reinterpret_cast<ulonglong2*>(&Ws[2048 + c * 64 + l * 4]);
            ulonglong2 w2 = *reinterpret_cast<ulonglong2*>(&Ws[4096 + c * 64 + l * 4]);
#pragma unroll
            for (int i = 0; i < 3; i++) {
                int tl = g + 16 * i;
                unsigned long long a0 = bc2(ins[0][tl][c]);
                unsigned long long a1 = bc2(ins[1][tl][c]);
                unsigned long long a2 = bc2(ins[2][tl][c]);
                FMA2(acc[i][0], a0, w0.x, acc[i][0]);
                FMA2(acc[i][1], a0, w0.y, acc[i][1]);
                FMA2(acc[i][0], a1, w1.x, acc[i][0]);
                FMA2(acc[i][1], a1, w1.y, acc[i][1]);
                FMA2(acc[i][0], a2, w2.x, acc[i][0]);
                FMA2(acc[i][1], a2, w2.y, acc[i][1]);
            }
        }
#pragma unroll
        for (int i = 0; i < 3; i++) {
            int tb = h * 48 + g + 16 * i;
            float2 lo = up2(acc[i][0]), hi = up2(acc[i][1]);
            float4 v;
            v.x = lo.x > 0.f ? lo.x : 0.f;
            v.y = lo.y > 0.f ? lo.y : 0.f;
            v.z = hi.x > 0.f ? hi.x : 0.f;
            v.w = hi.y > 0.f ? hi.y : 0.f;
            *reinterpret_cast<float4*>(g_cheb + (long)n * (TBD * FCH) + tb * FCH + l * 4) = v;
        }
    }
}

// ---------------- fused temporal conv + residual + relu + LN + transpose ----
// dyn smem floats: tw 12288 | res 2048 | x 3072 | vec 256 | cheb/z 97*68=6596
#define SMF_TW 0
#define SMF_RS 12288
#define SMF_XS 14336
#define SMF_VS 17408
#define SMF_CH 17664
#define SMF_TOTAL (17664 + 97 * 68)   // 24260 floats = 97040 bytes

__global__ __launch_bounds__(512, 1)
void k_final(const float* __restrict__ X,  const float* __restrict__ tw,
             const float* __restrict__ tbv, const float* __restrict__ rw,
             const float* __restrict__ rb,  const float* __restrict__ lg,
             const float* __restrict__ lb,  float* __restrict__ out) {
    extern __shared__ __align__(16) float sm[];
    float* TWs = sm + SMF_TW;   // [tap][fc][f]
    float* RSs = sm + SMF_RS;   // [c][f]
    float* XSs = sm + SMF_XS;   // [b][c][t]
    float* VSs = sm + SMF_VS;   // time_b | res_b | ln_g | ln_b
    float* CHs = sm + SMF_CH;   // [p][f] stride 68; row 96 = zero sentinel
    int n = blockIdx.x, tid = threadIdx.x;

    for (int i = tid; i < 12288; i += 512) {
        int tap = i >> 12, fc = (i >> 6) & 63, f = i & 63;
        TWs[i] = tw[(f * 64 + fc) * 3 + tap];
    }
    for (int i = tid; i < 2048; i += 512) {
        int c = i >> 6, f = i & 63;
        RSs[i] = rw[f * 32 + c];
    }
    for (int i = tid; i < 3072; i += 512)
        XSs[i] = X[((long)(i / 384) * N_NODES + n) * 384 + (i % 384)];
    if (tid < 64) {
        VSs[tid] = tbv[tid]; VSs[64 + tid] = rb[tid];
        VSs[128 + tid] = lg[tid]; VSs[192 + tid] = lb[tid];
    }
    for (int i4 = tid; i4 < 1536; i4 += 512) {
        int p = i4 >> 4, q = i4 & 15;
        *reinterpret_cast<float4*>(&CHs[p * 68 + q * 4]) =
            *reinterpret_cast<const float4*>(g_cheb + (long)n * 6144 + i4 * 4);
    }
    if (tid < 17)
        *reinterpret_cast<float4*>(&CHs[96 * 68 + tid * 4]) = make_float4(0.f, 0.f, 0.f, 0.f);
    __syncthreads();

    int l = tid & 15, g = tid >> 4;        // f = l*4+j (j<4), pairs p = g+32i (i<3)
    int pv[3], pmv[3], ppv[3], pbv[3], ptv[3];
#pragma unroll
    for (int i = 0; i < 3; i++) {
        int p = g + 32 * i;
        pv[i] = p; pbv[i] = p / 12; ptv[i] = p % 12;
        pmv[i] = (ptv[i] > 0)  ? p - 1 : 96;   // sentinel zero row
        ppv[i] = (ptv[i] < 11) ? p + 1 : 96;
    }
    unsigned long long acc[3][2];
    {
        float4 b0 = *reinterpret_cast<float4*>(&VSs[l * 4]);
        float4 b1 = *reinterpret_cast<float4*>(&VSs[64 + l * 4]);
#pragma unroll
        for (int i = 0; i < 3; i++) {
            acc[i][0] = pk2(b0.x + b1.x, b0.y + b1.y);
            acc[i][1] = pk2(b0.z + b1.z, b0.w + b1.w);
        }
    }

    // temporal conv (1x3 over t, zero-padded via sentinel row), fc unrolled x4
    for (int fc4 = 0; fc4 < 64; fc4 += 4) {
        ulonglong2 w[3][4];
#pragma unroll
        for (int tap = 0; tap < 3; tap++)
#pragma unroll
            for (int fq = 0; fq < 4; fq++)
                w[tap][fq] = *reinterpret_cast<ulonglong2*>(
                    &TWs[tap * 4096 + (fc4 + fq) * 64 + l * 4]);
#pragma unroll
        for (int i = 0; i < 3; i++) {
            float4 cm = *reinterpret_cast<float4*>(&CHs[pmv[i] * 68 + fc4]);
            float4 c0 = *reinterpret_cast<float4*>(&CHs[pv[i]  * 68 + fc4]);
            float4 cp = *reinterpret_cast<float4*>(&CHs[ppv[i] * 68 + fc4]);
            const float cmv[4] = {cm.x, cm.y, cm.z, cm.w};
            const float c0v[4] = {c0.x, c0.y, c0.z, c0.w};
            const float cpv[4] = {cp.x, cp.y, cp.z, cp.w};
#pragma unroll
            for (int fq = 0; fq < 4; fq++) {
                unsigned long long am = bc2(cmv[fq]);
                unsigned long long a0 = bc2(c0v[fq]);
                unsigned long long ap = bc2(cpv[fq]);
                FMA2(acc[i][0], am, w[0][fq].x, acc[i][0]);
                FMA2(acc[i][1], am, w[0][fq].y, acc[i][1]);
                FMA2(acc[i][0], a0, w[1][fq].x, acc[i][0]);
                FMA2(acc[i][1], a0, w[1][fq].y, acc[i][1]);
                FMA2(acc[i][0], ap, w[2][fq].x, acc[i][0]);
                FMA2(acc[i][1], ap, w[2][fq].y, acc[i][1]);
            }
        }
    }
    // residual 1x1 conv on raw X
    for (int c = 0; c < 32; c++) {
        ulonglong2 rv = *reinterpret_cast<ulonglong2*>(&RSs[c * 64 + l * 4]);
#pragma unroll
        for (int i = 0; i < 3; i++) {
            unsigned long long xv = bc2(XSs[pbv[i] * 384 + c * 12 + ptv[i]]);
            FMA2(acc[i][0], xv, rv.x, acc[i][0]);
            FMA2(acc[i][1], xv, rv.y, acc[i][1]);
        }
    }

    __syncthreads();                        // all CHs reads done; reuse as z
#pragma unroll
    for (int i = 0; i < 3; i++) {
        float2 lo = up2(acc[i][0]), hi = up2(acc[i][1]);
        float4 v;
        v.x = lo.x > 0.f ? lo.x : 0.f;
        v.y = lo.y > 0.f ? lo.y : 0.f;
        v.z = hi.x > 0.f ? hi.x : 0.f;
        v.w = hi.y > 0.f ? hi.y : 0.f;
        *reinterpret_cast<float4*>(&CHs[pv[i] * 68 + l * 4]) = v;
    }
    __syncthreads();

    // LayerNorm over f (64) per (b,t) row; warp-shuffle reduction
    int wrp = tid >> 5, lane = tid & 31;
    for (int i2 = 0; i2 < 6; i2++) {
        int p = wrp + 16 * i2;
        float v0 = CHs[p * 68 + lane], v1 = CHs[p * 68 + lane + 32];
        float s = v0 + v1, sq = v0 * v0 + v1 * v1;
#pragma unroll
        for (int o = 16; o; o >>= 1) {
            s  += __shfl_xor_sync(0xffffffffu, s,  o);
            sq += __shfl_xor_sync(0xffffffffu, sq, o);
        }
        float mu  = s * (1.f / 64.f);
        float var = sq * (1.f / 64.f) - mu * mu;
        float rs  = rsqrtf(var + 1e-5f);
        CHs[p * 68 + lane]      = (v0 - mu) * rs * VSs[128 + lane]      + VSs[192 + lane];
        CHs[p * 68 + lane + 32] = (v1 - mu) * rs * VSs[128 + lane + 32] + VSs[192 + lane + 32];
    }
    __syncthreads();

    // transposed coalesced output: out[b,n,f,t]
    {
        int b = tid >> 6, f = tid & 63;
        float* o = out + (((long)b * N_NODES + n) * 64 + f) * 12;
#pragma unroll
        for (int q = 0; q < 3; q++) {
            float4 v;
            v.x = CHs[(b * 12 + 4 * q + 0) * 68 + f];
            v.y = CHs[(b * 12 + 4 * q + 1) * 68 + f];
            v.z = CHs[(b * 12 + 4 * q + 2) * 68 + f];
            v.w = CHs[(b * 12 + 4 * q + 3) * 68 + f];
            *reinterpret_cast<float4*>(o + 4 * q) = v;
        }
    }
}

// ---------------- launch -----------------------------------------------------
extern "C" void kernel_launch(void* const* d_in, const int* in_sizes, int n_in,
                              void* d_out, int out_size) {
    (void)in_sizes; (void)n_in; (void)out_size;
    const float* X    = (const float*)d_in[0];
    const int*   ei   = (const int*)  d_in[1];
    const float* ew   = (const float*)d_in[2];
    const float* lmax = (const float*)d_in[3];
    const float* Wc   = (const float*)d_in[4];
    const float* bc   = (const float*)d_in[5];
    const float* tw   = (const float*)d_in[6];
    const float* tb   = (const float*)d_in[7];
    const float* rw   = (const float*)d_in[8];
    const float* rb   = (const float*)d_in[9];
    const float* lg   = (const float*)d_in[10];
    const float* lb   = (const float*)d_in[11];
    float* out = (float*)d_out;

    static bool attr_done = false;
    if (!attr_done) {
        cudaFuncSetAttribute(k_final, cudaFuncAttributeMaxDynamicSharedMemorySize,
                             SMF_TOTAL * (int)sizeof(float));
        attr_done = true;
    }

    k_init   <<<(N_NODES + 255) / 256, 256>>>();
    k_edges  <<<(E_EDGES + 255) / 256, 256>>>(ei, ew);
    k_scan   <<<1, 1024>>>();
    k_prep   <<<(N_NODES + 255) / 256, 256>>>(lmax);
    k_scatter<<<(E_EDGES + 255) / 256, 256>>>(ei, ew, lmax);
    k_buildx0<<<(BB * N_NODES * CIN * TT + 255) / 256, 256>>>(X);
    k_prop<0><<<N_NODES, 256>>>();
    k_prop<1><<<N_NODES, 256>>>();
    k_cheb   <<<N_NODES, 256>>>(Wc, bc);
    k_final  <<<N_NODES, 512, SMF_TOTAL * (int)sizeof(float)>>>(X, tw, tb, rw, rb, lg, lb, out);
}